// round 1
// baseline (speedup 1.0000x reference)
#include <cuda_runtime.h>
#include <cstdint>

// ---------------------------------------------------------------------------
// Problem shape constants
//   x: (4096, 1, 84, 84) -> conv1 8x8 s4 -> (4096,32,20,20)
//                         -> conv2 4x4 s2 -> (4096,64,9,9)
//                         -> conv3 3x3 s1 -> (4096,64,7,7) -> flat 3136
//   FC 3136->512 relu, LSTM T=128 B=32 H=128, heads A=6 + value
// Output layout assumed: [logits (4096*6), value (4096), hT (32*128), cT (32*128)]
// ---------------------------------------------------------------------------

#define NIMG   4096
#define TSTEPS 128
#define BATCH  32
#define HID    128

// Scratch (device globals; no allocation allowed)
__device__ float g_z1[(size_t)NIMG * 4 * 400 * 8];    // conv1 out, [n][g=oc/8][pix400][oc%8]
__device__ float g_z2[(size_t)NIMG * 4 * 81 * 16];    // conv2 out, [n][cc=oc/16][pix81][oc%16]
__device__ float g_z3[(size_t)NIMG * 3136];           // conv3 out, NCHW flatten (torch order)
__device__ float g_hidden[(size_t)NIMG * 512];        // FC out
__device__ float g_gates[(size_t)NIMG * 512];         // x-projection of gates (+both biases)
__device__ float g_hs[(size_t)NIMG * HID];            // per-step hidden outputs
__device__ float g_h[2 * BATCH * HID];                // LSTM h ping-pong
__device__ unsigned g_bar_cnt = 0;                    // grid barrier (self-resetting)
__device__ unsigned g_bar_gen = 0;

// ---------------------------------------------------------------------------
// conv1: 1x84x84 -> 32x20x20, k=8, s=4.  One block per image.
// ---------------------------------------------------------------------------
__global__ void conv1_kernel(const float* __restrict__ x,
                             const float* __restrict__ W1,
                             const float* __restrict__ b1) {
    __shared__ float img[84 * 84];
    __shared__ float ws[64 * 32];   // [k][oc]
    __shared__ float bs[32];
    const int n = blockIdx.x;
    const int tid = threadIdx.x;
    const float* xin = x + (size_t)n * 7056;
    for (int i = tid; i < 7056; i += 512) img[i] = xin[i] * (1.0f / 255.0f);
    for (int i = tid; i < 2048; i += 512) {
        int k = i >> 5, oc = i & 31;
        ws[i] = W1[oc * 64 + k];
    }
    if (tid < 32) bs[tid] = b1[tid];
    __syncthreads();

    if (tid < 400) {
        const int oy = tid / 20, ox = tid % 20;
        const int iy = oy * 4, ix = ox * 4;
        float acc[32];
#pragma unroll
        for (int o = 0; o < 32; o++) acc[o] = 0.f;
#pragma unroll
        for (int ky = 0; ky < 8; ky++) {
            const float* ip = &img[(iy + ky) * 84 + ix];
            float v[8];
#pragma unroll
            for (int kx = 0; kx < 8; kx++) v[kx] = ip[kx];
#pragma unroll
            for (int kx = 0; kx < 8; kx++) {
                const float* wp = &ws[(ky * 8 + kx) * 32];
                float vv = v[kx];
#pragma unroll
                for (int o = 0; o < 32; o++) acc[o] += vv * wp[o];
            }
        }
        float* zp = g_z1 + (size_t)n * 12800;
#pragma unroll
        for (int o = 0; o < 32; o++) {
            float r = fmaxf(acc[o] + bs[o], 0.f);
            int g = o >> 3, l = o & 7;
            zp[(g * 400 + tid) * 8 + l] = r;
        }
    }
}

// ---------------------------------------------------------------------------
// conv2: 32x20x20 -> 64x9x9, k=4, s=2. One block per image, ic chunked by 8.
// ---------------------------------------------------------------------------
__global__ void conv2_kernel(const float* __restrict__ W2,
                             const float* __restrict__ b2) {
    __shared__ float in_s[400 * 8];     // [pix][ic8]
    __shared__ float w_s[64 * 16 * 8];  // [oc][k16][ic8]
    const int n = blockIdx.x;
    const int tid = threadIdx.x;
    const int ocg = tid / 81, p = tid % 81;
    const int oy = p / 9, ox = p % 9;
    const bool active = (tid < 648);
    float acc[8];
#pragma unroll
    for (int o = 0; o < 8; o++) acc[o] = 0.f;

    for (int c = 0; c < 4; c++) {
        __syncthreads();
        const float* zin = g_z1 + ((size_t)n * 4 + c) * 3200;
        for (int i = tid; i < 3200; i += blockDim.x) in_s[i] = zin[i];
        for (int i = tid; i < 8192; i += blockDim.x) {
            int oc = i >> 7, r = i & 127, k = r >> 3, icl = r & 7;
            w_s[i] = W2[oc * 512 + (c * 8 + icl) * 16 + k];
        }
        __syncthreads();
        if (active) {
#pragma unroll
            for (int k = 0; k < 16; k++) {
                const int ky = k >> 2, kx = k & 3;
                const float4* ip =
                    (const float4*)&in_s[((oy * 2 + ky) * 20 + (ox * 2 + kx)) * 8];
                const float4 a0 = ip[0], a1 = ip[1];
#pragma unroll
                for (int o = 0; o < 8; o++) {
                    const float4* wp = (const float4*)&w_s[((ocg * 8 + o) * 16 + k) * 8];
                    const float4 w0 = wp[0], w1 = wp[1];
                    acc[o] += a0.x * w0.x + a0.y * w0.y + a0.z * w0.z + a0.w * w0.w +
                              a1.x * w1.x + a1.y * w1.y + a1.z * w1.z + a1.w * w1.w;
                }
            }
        }
    }
    if (active) {
#pragma unroll
        for (int o = 0; o < 8; o++) {
            int oc = ocg * 8 + o;
            float r = fmaxf(acc[o] + b2[oc], 0.f);
            g_z2[(((size_t)n * 4 + (oc >> 4)) * 81 + p) * 16 + (oc & 15)] = r;
        }
    }
}

// ---------------------------------------------------------------------------
// conv3: 64x9x9 -> 64x7x7, k=3, s=1. One block per image, ic chunked by 16.
// Output written NCHW (torch flatten order) for the FC GEMM.
// ---------------------------------------------------------------------------
__global__ void conv3_kernel(const float* __restrict__ W3,
                             const float* __restrict__ b3) {
    __shared__ float in_s[81 * 16];     // [pix][ic16]
    __shared__ float w_s[64 * 9 * 16];  // [oc][k9][ic16]
    const int n = blockIdx.x;
    const int tid = threadIdx.x;
    const int ocg = tid / 49, p = tid % 49;
    const int oy = p / 7, ox = p % 7;
    const bool active = (tid < 392);
    float acc[8];
#pragma unroll
    for (int o = 0; o < 8; o++) acc[o] = 0.f;

    for (int cc = 0; cc < 4; cc++) {
        __syncthreads();
        const float* zin = g_z2 + ((size_t)n * 4 + cc) * 1296;
        for (int i = tid; i < 1296; i += blockDim.x) in_s[i] = zin[i];
        for (int i = tid; i < 9216; i += blockDim.x) {
            int oc = i / 144, r = i % 144, k = r >> 4, icl = r & 15;
            w_s[i] = W3[oc * 576 + (cc * 16 + icl) * 9 + k];
        }
        __syncthreads();
        if (active) {
#pragma unroll
            for (int k = 0; k < 9; k++) {
                const int ky = k / 3, kx = k % 3;
                const float4* ip = (const float4*)&in_s[((oy + ky) * 9 + (ox + kx)) * 16];
                const float4 a0 = ip[0], a1 = ip[1], a2 = ip[2], a3 = ip[3];
#pragma unroll
                for (int o = 0; o < 8; o++) {
                    const float4* wp = (const float4*)&w_s[((ocg * 8 + o) * 9 + k) * 16];
                    const float4 w0 = wp[0], w1 = wp[1], w2 = wp[2], w3 = wp[3];
                    acc[o] += a0.x * w0.x + a0.y * w0.y + a0.z * w0.z + a0.w * w0.w +
                              a1.x * w1.x + a1.y * w1.y + a1.z * w1.z + a1.w * w1.w +
                              a2.x * w2.x + a2.y * w2.y + a2.z * w2.z + a2.w * w2.w +
                              a3.x * w3.x + a3.y * w3.y + a3.z * w3.z + a3.w * w3.w;
                }
            }
        }
    }
    if (active) {
#pragma unroll
        for (int o = 0; o < 8; o++) {
            int oc = ocg * 8 + o;
            float r = fmaxf(acc[o] + b3[oc], 0.f);
            g_z3[(size_t)n * 3136 + oc * 49 + p] = r;
        }
    }
}

// ---------------------------------------------------------------------------
// GEMM: C[M,N] = A[M,K] * B[N,K]^T + bias(+bias2), optional relu.
// BM=BN=64, BK=16, 256 threads, 4x4 microtile. M=4096, N=512 fixed shapes.
// ---------------------------------------------------------------------------
__device__ __forceinline__ void gemm_body(const float* __restrict__ A,
                                          const float* __restrict__ B,
                                          float* __restrict__ C, int K,
                                          const float* __restrict__ bias1,
                                          const float* __restrict__ bias2,
                                          bool relu) {
    __shared__ float As[16 * 68];
    __shared__ float Bs[16 * 68];
    const int tid = threadIdx.x;
    const int m0 = blockIdx.y * 64, n0 = blockIdx.x * 64;
    const int ar = tid >> 2, ac = (tid & 3) << 2;
    const int tx = tid & 15, ty = tid >> 4;
    const int N = 512;

    float acc[4][4];
#pragma unroll
    for (int i = 0; i < 4; i++)
#pragma unroll
        for (int j = 0; j < 4; j++) acc[i][j] = 0.f;

    const float* Ap = A + (size_t)(m0 + ar) * K + ac;
    const float* Bp = B + (size_t)(n0 + ar) * K + ac;

    for (int k0 = 0; k0 < K; k0 += 16) {
        const float4 av = *(const float4*)(Ap + k0);
        const float4 bv = *(const float4*)(Bp + k0);
        As[(ac + 0) * 68 + ar] = av.x;
        As[(ac + 1) * 68 + ar] = av.y;
        As[(ac + 2) * 68 + ar] = av.z;
        As[(ac + 3) * 68 + ar] = av.w;
        Bs[(ac + 0) * 68 + ar] = bv.x;
        Bs[(ac + 1) * 68 + ar] = bv.y;
        Bs[(ac + 2) * 68 + ar] = bv.z;
        Bs[(ac + 3) * 68 + ar] = bv.w;
        __syncthreads();
#pragma unroll
        for (int kk = 0; kk < 16; kk++) {
            const float4 a = *(const float4*)&As[kk * 68 + (ty << 2)];
            const float4 b = *(const float4*)&Bs[kk * 68 + (tx << 2)];
            acc[0][0] += a.x * b.x; acc[0][1] += a.x * b.y;
            acc[0][2] += a.x * b.z; acc[0][3] += a.x * b.w;
            acc[1][0] += a.y * b.x; acc[1][1] += a.y * b.y;
            acc[1][2] += a.y * b.z; acc[1][3] += a.y * b.w;
            acc[2][0] += a.z * b.x; acc[2][1] += a.z * b.y;
            acc[2][2] += a.z * b.z; acc[2][3] += a.z * b.w;
            acc[3][0] += a.w * b.x; acc[3][1] += a.w * b.y;
            acc[3][2] += a.w * b.z; acc[3][3] += a.w * b.w;
        }
        __syncthreads();
    }

    float bb[4];
#pragma unroll
    for (int j = 0; j < 4; j++) {
        int nn = n0 + (tx << 2) + j;
        bb[j] = bias1[nn] + (bias2 ? bias2[nn] : 0.f);
    }
#pragma unroll
    for (int i = 0; i < 4; i++) {
        float4 o;
        float v0 = acc[i][0] + bb[0], v1 = acc[i][1] + bb[1];
        float v2 = acc[i][2] + bb[2], v3 = acc[i][3] + bb[3];
        if (relu) {
            v0 = fmaxf(v0, 0.f); v1 = fmaxf(v1, 0.f);
            v2 = fmaxf(v2, 0.f); v3 = fmaxf(v3, 0.f);
        }
        o.x = v0; o.y = v1; o.z = v2; o.w = v3;
        *(float4*)&C[(size_t)(m0 + (ty << 2) + i) * N + n0 + (tx << 2)] = o;
    }
}

__global__ void fc_gemm_kernel(const float* __restrict__ Wfc,
                               const float* __restrict__ bfc) {
    gemm_body(g_z3, Wfc, g_hidden, 3136, bfc, nullptr, true);
}
__global__ void gates_gemm_kernel(const float* __restrict__ W_ih,
                                  const float* __restrict__ b_ih,
                                  const float* __restrict__ b_hh) {
    gemm_body(g_hidden, W_ih, g_gates, 512, b_ih, b_hh, false);
}

// ---------------------------------------------------------------------------
// LSTM: single kernel, 32 blocks x 128 threads, grid barrier per step.
// Block m owns hidden units j0=4m..4m+3 (16 gate rows). c lives in registers.
// ---------------------------------------------------------------------------
__device__ __forceinline__ void grid_barrier(unsigned nb) {
    __threadfence();
    __syncthreads();
    if (threadIdx.x == 0) {
        unsigned gen = *((volatile unsigned*)&g_bar_gen);
        unsigned a = atomicAdd(&g_bar_cnt, 1u);
        if (a == nb - 1u) {
            g_bar_cnt = 0u;
            __threadfence();
            atomicExch(&g_bar_gen, gen + 1u);
        } else {
            while (*((volatile unsigned*)&g_bar_gen) == gen) __nanosleep(32);
        }
    }
    __syncthreads();
}

__device__ __forceinline__ float sigmoidf_(float v) {
    return 1.0f / (1.0f + expf(-v));
}

__global__ void lstm_kernel(const float* __restrict__ done,
                            const float* __restrict__ W_hh,
                            const float* __restrict__ h0,
                            const float* __restrict__ c0,
                            float* __restrict__ out) {
    __shared__ float Ws[16 * 128];     // 16 gate rows for this block
    __shared__ float hsb[BATCH * HID]; // full previous h
    __shared__ float gsb[BATCH * 16];  // gate values for this block's units
    const int tid = threadIdx.x;
    const int j0 = blockIdx.x * 4;

    // load this block's 16 W_hh rows: local l -> row j0 + (l>>2) + (l&3)*128
    for (int i = tid; i < 2048; i += 128) {
        int l = i >> 7, k = i & 127;
        int row = j0 + (l >> 2) + (l & 3) * 128;
        Ws[i] = W_hh[row * 128 + k];
    }
    // update-role indices
    const int ub = tid >> 2, uu = tid & 3, uj = j0 + uu;
    float c_reg = c0[ub * 128 + uj];
    // dot-role indices: tile = (4 b's) x (unit lg, 4 gates), k split by 4
    const int tile = tid >> 2, ks = tid & 3;
    const int b0 = (tile >> 2) * 4;
    const int lg = tile & 3;
    const int l0 = lg * 4;
    const int kbase = ks * 32;
    __syncthreads();

    for (int t = 0; t < TSTEPS; t++) {
        if (t == 0) {
            for (int i = tid; i < BATCH * HID; i += 128) hsb[i] = h0[i];
        } else {
            const float* hsrc = &g_h[((t - 1) & 1) * BATCH * HID];
            for (int i = tid; i < BATCH * HID; i += 128) hsb[i] = __ldcg(&hsrc[i]);
        }
        __syncthreads();

        float acc[4][4];
#pragma unroll
        for (int i = 0; i < 4; i++)
#pragma unroll
            for (int j = 0; j < 4; j++) acc[i][j] = 0.f;

#pragma unroll
        for (int kk = 0; kk < 32; kk += 4) {
            const int k = kbase + kk;
            float4 h4[4], w4[4];
#pragma unroll
            for (int i = 0; i < 4; i++)
                h4[i] = *(const float4*)&hsb[(b0 + i) * 128 + k];
#pragma unroll
            for (int j = 0; j < 4; j++)
                w4[j] = *(const float4*)&Ws[(l0 + j) * 128 + k];
#pragma unroll
            for (int i = 0; i < 4; i++)
#pragma unroll
                for (int j = 0; j < 4; j++)
                    acc[i][j] += h4[i].x * w4[j].x + h4[i].y * w4[j].y +
                                 h4[i].z * w4[j].z + h4[i].w * w4[j].w;
        }
        // reduce partial dots across the 4 k-splits (low 2 lane bits)
#pragma unroll
        for (int i = 0; i < 4; i++)
#pragma unroll
            for (int j = 0; j < 4; j++) {
                float v = acc[i][j];
                v += __shfl_xor_sync(0xffffffffu, v, 1);
                v += __shfl_xor_sync(0xffffffffu, v, 2);
                acc[i][j] = v;
            }
        if (ks == 0) {
#pragma unroll
            for (int i = 0; i < 4; i++) {
                const int b = b0 + i;
                const float mask = 1.0f - done[t * BATCH + b];
                const float* gxp = &g_gates[(size_t)(t * BATCH + b) * 512];
#pragma unroll
                for (int j = 0; j < 4; j++) {
                    const int row = j0 + lg + j * 128;
                    gsb[b * 16 + lg * 4 + j] = gxp[row] + mask * acc[i][j];
                }
            }
        }
        __syncthreads();
        {
            const float gi = gsb[ub * 16 + uu * 4 + 0];
            const float gf = gsb[ub * 16 + uu * 4 + 1];
            const float gg = gsb[ub * 16 + uu * 4 + 2];
            const float go = gsb[ub * 16 + uu * 4 + 3];
            const float mask = 1.0f - done[t * BATCH + ub];
            const float cn = sigmoidf_(gf) * (c_reg * mask) + sigmoidf_(gi) * tanhf(gg);
            const float hn = sigmoidf_(go) * tanhf(cn);
            c_reg = cn;
            g_h[(t & 1) * BATCH * HID + ub * 128 + uj] = hn;
            g_hs[(size_t)(t * BATCH + ub) * 128 + uj] = hn;
            if (t == TSTEPS - 1) {
                out[28672 + ub * 128 + uj] = hn;     // hT
                out[32768 + ub * 128 + uj] = c_reg;  // cT
            }
        }
        if (t < TSTEPS - 1) grid_barrier(gridDim.x);
    }
}

// ---------------------------------------------------------------------------
// Heads: logits (4096x6) and value (4096x1) from g_hs.
// ---------------------------------------------------------------------------
__global__ void heads_kernel(const float* __restrict__ Wa,
                             const float* __restrict__ ba,
                             const float* __restrict__ Wc,
                             const float* __restrict__ bc,
                             float* __restrict__ out) {
    __shared__ float was[6 * 128];
    __shared__ float wcs[128];
    __shared__ float bas[6];
    __shared__ float bcs;
    const int tid = threadIdx.x;
    for (int i = tid; i < 768; i += 256) was[i] = Wa[i];
    if (tid < 128) wcs[tid] = Wc[tid];
    if (tid < 6) bas[tid] = ba[tid];
    if (tid == 0) bcs = bc[0];
    __syncthreads();

    const int row = blockIdx.x * 256 + tid;
    const float* hp = &g_hs[(size_t)row * 128];
    float acc[6] = {0.f, 0.f, 0.f, 0.f, 0.f, 0.f};
    float accv = 0.f;
    for (int k = 0; k < 128; k += 4) {
        const float4 h4 = *(const float4*)&hp[k];
#pragma unroll
        for (int a = 0; a < 6; a++) {
            const float4 w4 = *(const float4*)&was[a * 128 + k];
            acc[a] += h4.x * w4.x + h4.y * w4.y + h4.z * w4.z + h4.w * w4.w;
        }
        const float4 wc4 = *(const float4*)&wcs[k];
        accv += h4.x * wc4.x + h4.y * wc4.y + h4.z * wc4.z + h4.w * wc4.w;
    }
#pragma unroll
    for (int a = 0; a < 6; a++) out[row * 6 + a] = acc[a] + bas[a];
    out[24576 + row] = accv + bcs;
}

// ---------------------------------------------------------------------------
// Launch
// ---------------------------------------------------------------------------
extern "C" void kernel_launch(void* const* d_in, const int* in_sizes, int n_in,
                              void* d_out, int out_size) {
    const float* x    = (const float*)d_in[0];
    const float* done = (const float*)d_in[1];
    const float* h0   = (const float*)d_in[2];
    const float* c0   = (const float*)d_in[3];
    const float* W1   = (const float*)d_in[4];
    const float* b1   = (const float*)d_in[5];
    const float* W2   = (const float*)d_in[6];
    const float* b2   = (const float*)d_in[7];
    const float* W3   = (const float*)d_in[8];
    const float* b3   = (const float*)d_in[9];
    const float* Wfc  = (const float*)d_in[10];
    const float* bfc  = (const float*)d_in[11];
    const float* W_ih = (const float*)d_in[12];
    const float* W_hh = (const float*)d_in[13];
    const float* b_ih = (const float*)d_in[14];
    const float* b_hh = (const float*)d_in[15];
    const float* Wa   = (const float*)d_in[16];
    const float* ba   = (const float*)d_in[17];
    const float* Wc   = (const float*)d_in[18];
    const float* bc   = (const float*)d_in[19];
    float* out = (float*)d_out;

    conv1_kernel<<<NIMG, 512>>>(x, W1, b1);
    conv2_kernel<<<NIMG, 672>>>(W2, b2);
    conv3_kernel<<<NIMG, 416>>>(W3, b3);
    fc_gemm_kernel<<<dim3(8, 64), 256>>>(Wfc, bfc);
    gates_gemm_kernel<<<dim3(8, 64), 256>>>(W_ih, b_ih, b_hh);
    lstm_kernel<<<32, 128>>>(done, W_hh, h0, c0, out);
    heads_kernel<<<16, 256>>>(Wa, ba, Wc, bc, out);
}